// round 1
// baseline (speedup 1.0000x reference)
#include <cuda_runtime.h>
#include <cuda_bf16.h>

#define BATCH   4
#define TSEQ    1024
#define CDIM    1024
#define NHEADS  16
#define HDIM    64
#define M_ROWS  (BATCH * TSEQ)   // 4096

// -------- scratch (device globals; no allocations allowed) --------
__device__ float g_qp[BATCH * NHEADS * TSEQ * HDIM];   // [B,H,T,D]
__device__ float g_kp[BATCH * NHEADS * TSEQ * HDIM];
__device__ float g_vp[BATCH * NHEADS * TSEQ * HDIM];
__device__ float g_attn[M_ROWS * CDIM];                // [B*T, C]

// ============================================================================
// Tiled NT SGEMM:  C[m,n] = sum_k A[m,k] * W[n,k] + bias[n]
// A: [M=4096, K=1024] row-major, W: [N=1024, K=1024] row-major.
// BM=BN=128, BK=16, 256 threads, 8x8 per thread.
// MODE 0: write C row-major [M, N] (output projection -> d_out)
// MODE 1: write head layout [B, H, T, D]  (Q/K/V projections)
// ============================================================================
template <int MODE>
__global__ void __launch_bounds__(256) gemm_nt_kernel(
    const float* __restrict__ A,
    const float* __restrict__ W,
    const float* __restrict__ bias,
    float* __restrict__ C)
{
    const int BK  = 16;
    const int LDS = 132;   // padded stride (conflict-free transposed stores)

    __shared__ float As[16 * 132];
    __shared__ float Bs[16 * 132];

    const int tid = threadIdx.x;
    const int tx  = tid & 15;      // 0..15
    const int ty  = tid >> 4;      // 0..15
    const int m0  = blockIdx.y * 128;
    const int n0  = blockIdx.x * 128;

    float acc[8][8];
#pragma unroll
    for (int i = 0; i < 8; i++)
#pragma unroll
        for (int j = 0; j < 8; j++) acc[i][j] = 0.f;

    for (int k0 = 0; k0 < CDIM; k0 += BK) {
        // ---- load + transpose A and W tiles into smem ----
#pragma unroll
        for (int it = 0; it < 2; it++) {
            int i    = tid + it * 256;     // 0..511
            int arow = i >> 2;             // 0..127
            int acol = (i & 3) * 4;        // 0,4,8,12
            float4 va = *(const float4*)&A[(size_t)(m0 + arow) * CDIM + k0 + acol];
            As[(acol + 0) * LDS + arow] = va.x;
            As[(acol + 1) * LDS + arow] = va.y;
            As[(acol + 2) * LDS + arow] = va.z;
            As[(acol + 3) * LDS + arow] = va.w;
            float4 vw = *(const float4*)&W[(size_t)(n0 + arow) * CDIM + k0 + acol];
            Bs[(acol + 0) * LDS + arow] = vw.x;
            Bs[(acol + 1) * LDS + arow] = vw.y;
            Bs[(acol + 2) * LDS + arow] = vw.z;
            Bs[(acol + 3) * LDS + arow] = vw.w;
        }
        __syncthreads();

#pragma unroll
        for (int kk = 0; kk < BK; kk++) {
            float4 a0 = *(const float4*)&As[kk * LDS + ty * 8];
            float4 a1 = *(const float4*)&As[kk * LDS + ty * 8 + 4];
            float4 b0 = *(const float4*)&Bs[kk * LDS + tx * 8];
            float4 b1 = *(const float4*)&Bs[kk * LDS + tx * 8 + 4];
            float ar[8] = {a0.x, a0.y, a0.z, a0.w, a1.x, a1.y, a1.z, a1.w};
            float br[8] = {b0.x, b0.y, b0.z, b0.w, b1.x, b1.y, b1.z, b1.w};
#pragma unroll
            for (int i = 0; i < 8; i++)
#pragma unroll
                for (int j = 0; j < 8; j++)
                    acc[i][j] += ar[i] * br[j];
        }
        __syncthreads();
    }

    // ---- epilogue: bias + store ----
#pragma unroll
    for (int i = 0; i < 8; i++) {
        int m = m0 + ty * 8 + i;
#pragma unroll
        for (int j = 0; j < 8; j++) {
            int n = n0 + tx * 8 + j;
            float val = acc[i][j] + bias[n];
            if (MODE == 0) {
                C[(size_t)m * CDIM + n] = val;
            } else {
                int b = m >> 10, t = m & 1023;
                int h = n >> 6,  d = n & 63;
                C[((((size_t)b * NHEADS + h) * TSEQ) + t) * HDIM + d] = val;
            }
        }
    }
}

// ============================================================================
// Flash-style attention. Q/K/V in [B,H,T,D] (D=64) fp32.
// Block: 128 threads, each owns one q row; grid (TSEQ/128, B*H).
// Per 64-row K/V tile: pass1 computes scores into smem (stride 65),
// online-softmax rescale, pass2 accumulates p*V. Output -> [B*T, C].
// ============================================================================
__global__ void __launch_bounds__(128) attn_kernel(
    const float* __restrict__ Q,
    const float* __restrict__ K,
    const float* __restrict__ V,
    float* __restrict__ O)
{
    extern __shared__ float sh[];
    float* Ks = sh;                 // 64*64
    float* Vs = sh + 64 * 64;       // 64*64
    float* Ss = sh + 2 * 64 * 64;   // 128*65

    const int t   = threadIdx.x;
    const int bh  = blockIdx.y;
    const int row = blockIdx.x * 128 + t;
    const float scale = 0.125f;     // 64^-0.5

    // load q row (pre-scaled)
    float q[64];
    const float* qptr = Q + ((size_t)bh * TSEQ + row) * HDIM;
#pragma unroll
    for (int d4 = 0; d4 < 16; d4++) {
        float4 v = *(const float4*)&qptr[d4 * 4];
        q[d4 * 4 + 0] = v.x * scale;
        q[d4 * 4 + 1] = v.y * scale;
        q[d4 * 4 + 2] = v.z * scale;
        q[d4 * 4 + 3] = v.w * scale;
    }

    float acc[64];
#pragma unroll
    for (int d = 0; d < 64; d++) acc[d] = 0.f;
    float mrow = -3.402823466e38f;
    float lsum = 0.f;

    const float* kbase = K + (size_t)bh * TSEQ * HDIM;
    const float* vbase = V + (size_t)bh * TSEQ * HDIM;

    for (int kt = 0; kt < TSEQ; kt += 64) {
        // load K,V tiles (4096 floats each); 128 threads * 8 float4
        const float* ksrc = kbase + (size_t)kt * HDIM;
        const float* vsrc = vbase + (size_t)kt * HDIM;
#pragma unroll
        for (int it = 0; it < 8; it++) {
            int idx = (t + it * 128) * 4;
            *(float4*)&Ks[idx] = *(const float4*)&ksrc[idx];
            *(float4*)&Vs[idx] = *(const float4*)&vsrc[idx];
        }
        __syncthreads();

        // pass 1: scores for this tile
        float tm = -3.402823466e38f;
#pragma unroll 4
        for (int j = 0; j < 64; j++) {
            float s = 0.f;
#pragma unroll
            for (int d = 0; d < 64; d++) s += q[d] * Ks[j * 64 + d];
            Ss[t * 65 + j] = s;
            tm = fmaxf(tm, s);
        }

        float mn    = fmaxf(mrow, tm);
        float alpha = __expf(mrow - mn);
        mrow = mn;
        lsum *= alpha;
#pragma unroll
        for (int d = 0; d < 64; d++) acc[d] *= alpha;

        // pass 2: p*V accumulation
#pragma unroll 2
        for (int j = 0; j < 64; j++) {
            float p = __expf(Ss[t * 65 + j] - mrow);
            lsum += p;
#pragma unroll
            for (int d = 0; d < 64; d++) acc[d] += p * Vs[j * 64 + d];
        }
        __syncthreads();
    }

    float inv = 1.f / lsum;
    int b = bh >> 4, h = bh & 15;
    float* optr = O + ((size_t)b * TSEQ + row) * CDIM + h * HDIM;
#pragma unroll
    for (int d4 = 0; d4 < 16; d4++) {
        float4 v;
        v.x = acc[d4 * 4 + 0] * inv;
        v.y = acc[d4 * 4 + 1] * inv;
        v.z = acc[d4 * 4 + 2] * inv;
        v.w = acc[d4 * 4 + 3] * inv;
        *(float4*)&optr[d4 * 4] = v;
    }
}

// ============================================================================
// kernel_launch
// inputs: q,k,v,Wq,bq,Wk,bk,Wv,bv,Wo,bo   output: [B,T,C] fp32
// ============================================================================
extern "C" void kernel_launch(void* const* d_in, const int* in_sizes, int n_in,
                              void* d_out, int out_size)
{
    const float* q  = (const float*)d_in[0];
    const float* k  = (const float*)d_in[1];
    const float* v  = (const float*)d_in[2];
    const float* Wq = (const float*)d_in[3];
    const float* bq = (const float*)d_in[4];
    const float* Wk = (const float*)d_in[5];
    const float* bk = (const float*)d_in[6];
    const float* Wv = (const float*)d_in[7];
    const float* bv = (const float*)d_in[8];
    const float* Wo = (const float*)d_in[9];
    const float* bo = (const float*)d_in[10];
    float* out = (float*)d_out;

    float *qp, *kp, *vp, *attn;
    cudaGetSymbolAddress((void**)&qp,   g_qp);
    cudaGetSymbolAddress((void**)&kp,   g_kp);
    cudaGetSymbolAddress((void**)&vp,   g_vp);
    cudaGetSymbolAddress((void**)&attn, g_attn);

    const int attn_smem = (64 * 64 * 2 + 128 * 65) * (int)sizeof(float); // 66048
    cudaFuncSetAttribute(attn_kernel, cudaFuncAttributeMaxDynamicSharedMemorySize, attn_smem);

    dim3 ggrid(CDIM / 128, M_ROWS / 128);  // (8, 32)
    dim3 gblock(256);

    gemm_nt_kernel<1><<<ggrid, gblock>>>(q, Wq, bq, qp);
    gemm_nt_kernel<1><<<ggrid, gblock>>>(k, Wk, bk, kp);
    gemm_nt_kernel<1><<<ggrid, gblock>>>(v, Wv, bv, vp);

    dim3 agrid(TSEQ / 128, BATCH * NHEADS);  // (8, 64)
    attn_kernel<<<agrid, 128, attn_smem>>>(qp, kp, vp, attn);

    gemm_nt_kernel<0><<<ggrid, gblock>>>(attn, Wo, bo, out);
}

// round 3
// speedup vs baseline: 1.5552x; 1.5552x over previous
#include <cuda_runtime.h>
#include <cuda_bf16.h>
#include <cstdint>

#define BATCH   4
#define TSEQ    1024
#define CDIM    1024
#define NHEADS  16
#define HDIM    64
#define M_ROWS  (BATCH * TSEQ)   // 4096

// ---------------- scratch (device globals; no allocations allowed) ----------
__device__ float g_qp[BATCH * NHEADS * TSEQ * HDIM];   // [B,H,T,D]
__device__ float g_kp[BATCH * NHEADS * TSEQ * HDIM];
__device__ float g_vp[BATCH * NHEADS * TSEQ * HDIM];
__device__ float g_attn[M_ROWS * CDIM];                // [B*T, C]
__device__ __nv_bfloat16 g_ahi[M_ROWS * CDIM];         // activation hi/lo (reused per GEMM)
__device__ __nv_bfloat16 g_alo[M_ROWS * CDIM];
__device__ __nv_bfloat16 g_whi[CDIM * CDIM];           // weight hi/lo (reused per GEMM)
__device__ __nv_bfloat16 g_wlo[CDIM * CDIM];

// ---------------- helpers ----------------------------------------------------
__device__ __forceinline__ uint32_t smem_u32(const void* p) {
    uint32_t a;
    asm("{ .reg .u64 t; cvta.to.shared.u64 t, %1; cvt.u32.u64 %0, t; }" : "=r"(a) : "l"(p));
    return a;
}
__device__ __forceinline__ void ldmatrix_x4(uint32_t* r, uint32_t addr) {
    asm volatile("ldmatrix.sync.aligned.m8n8.x4.shared.b16 {%0,%1,%2,%3}, [%4];"
        : "=r"(r[0]), "=r"(r[1]), "=r"(r[2]), "=r"(r[3]) : "r"(addr));
}
__device__ __forceinline__ void mma16816(float* d, const uint32_t* a, const uint32_t* b) {
    asm volatile("mma.sync.aligned.m16n8k16.row.col.f32.bf16.bf16.f32 "
        "{%0,%1,%2,%3}, {%4,%5,%6,%7}, {%8,%9}, {%0,%1,%2,%3};"
        : "+f"(d[0]), "+f"(d[1]), "+f"(d[2]), "+f"(d[3])
        : "r"(a[0]), "r"(a[1]), "r"(a[2]), "r"(a[3]), "r"(b[0]), "r"(b[1]));
}

// ============================================================================
// fp32 -> bf16 hi/lo split conversion (vectorized x4)
// ============================================================================
__global__ void __launch_bounds__(256) cvt_hilo_kernel(
    const float4* __restrict__ x,
    __nv_bfloat162* __restrict__ hi,
    __nv_bfloat162* __restrict__ lo,
    int n4)
{
    int i = blockIdx.x * blockDim.x + threadIdx.x;
    if (i >= n4) return;
    float4 v = x[i];
    __nv_bfloat16 hx = __float2bfloat16(v.x);
    __nv_bfloat16 hy = __float2bfloat16(v.y);
    __nv_bfloat16 hz = __float2bfloat16(v.z);
    __nv_bfloat16 hw = __float2bfloat16(v.w);
    __nv_bfloat16 lx = __float2bfloat16(v.x - __bfloat162float(hx));
    __nv_bfloat16 ly = __float2bfloat16(v.y - __bfloat162float(hy));
    __nv_bfloat16 lz = __float2bfloat16(v.z - __bfloat162float(hz));
    __nv_bfloat16 lw = __float2bfloat16(v.w - __bfloat162float(hw));
    __nv_bfloat162 h0; h0.x = hx; h0.y = hy;
    __nv_bfloat162 h1; h1.x = hz; h1.y = hw;
    __nv_bfloat162 l0; l0.x = lx; l0.y = ly;
    __nv_bfloat162 l1; l1.x = lz; l1.y = lw;
    hi[2 * i] = h0; hi[2 * i + 1] = h1;
    lo[2 * i] = l0; lo[2 * i + 1] = l1;
}

// ============================================================================
// HMMA (mma.sync m16n8k16 bf16) NT GEMM with hi/lo 3-pass split precision:
//   C[m,n] = sum_k A[m,k]*W[n,k] + bias[n]
//   acc += Ahi*Whi + Ahi*Wlo + Alo*Whi    (fp32 accumulate)
// CTA tile 128x128, 8 warps (4x2), warp tile 32x64, K-chunk 64 bf16.
// smem row stride 72 bf16 (144B) -> ldmatrix conflict-free.
// MODE 0: row-major [M,N].  MODE 1: head layout [B,H,T,D].
// ============================================================================
#define LDS 72   // bf16 units per smem row (64 data + 8 pad)

template <int MODE>
__global__ void __launch_bounds__(256) gemm_mma_kernel(
    const __nv_bfloat16* __restrict__ Ahi, const __nv_bfloat16* __restrict__ Alo,
    const __nv_bfloat16* __restrict__ Whi, const __nv_bfloat16* __restrict__ Wlo,
    const float* __restrict__ bias, float* __restrict__ C)
{
    extern __shared__ __nv_bfloat16 sm[];
    __nv_bfloat16* sAhi = sm;
    __nv_bfloat16* sAlo = sm + 128 * LDS;
    __nv_bfloat16* sWhi = sm + 2 * 128 * LDS;
    __nv_bfloat16* sWlo = sm + 3 * 128 * LDS;

    const int tid    = threadIdx.x;
    const int wid    = tid >> 5;
    const int lane   = tid & 31;
    const int warp_m = wid & 3;    // 0..3  -> 32 rows each
    const int warp_n = wid >> 2;   // 0..1  -> 64 cols each
    const int m0     = blockIdx.y * 128;
    const int n0     = blockIdx.x * 128;

    float acc[2][8][4];
#pragma unroll
    for (int i = 0; i < 2; i++)
#pragma unroll
        for (int j = 0; j < 8; j++)
#pragma unroll
            for (int r = 0; r < 4; r++) acc[i][j][r] = 0.f;

    // ldmatrix lane base addresses (bytes)
    // A (16x16 tiles): row = lane%16, colByte = (lane/16)*16
    const uint32_t aRowOff = (uint32_t)((warp_m * 32 + (lane & 15)) * LDS * 2 + (lane >> 4) * 16);
    const uint32_t uAhi = smem_u32(sAhi) + aRowOff;
    const uint32_t uAlo = smem_u32(sAlo) + aRowOff;
    // B (two 8-col tiles per x4): nrow = (lane&7) + ((lane>>4)<<3), kByte = ((lane>>3)&1)*16
    const uint32_t bRowOff = (uint32_t)((warp_n * 64 + (lane & 7) + ((lane >> 4) << 3)) * LDS * 2
                                        + ((lane >> 3) & 1) * 16);
    const uint32_t uWhi = smem_u32(sWhi) + bRowOff;
    const uint32_t uWlo = smem_u32(sWlo) + bRowOff;

    for (int c = 0; c < 16; ++c) {
        const int k0 = c * 64;
        // ---- load 4 tiles: 128 rows x 64 bf16 each ----
#pragma unroll
        for (int rep = 0; rep < 4; ++rep) {
            int idx = tid + rep * 256;        // 0..1023
            int row = idx >> 3;               // 0..127
            int c16 = idx & 7;                // 16B chunk
            int dst = row * LDS + c16 * 8;
            size_t aoff = (size_t)(m0 + row) * CDIM + k0 + c16 * 8;
            size_t woff = (size_t)(n0 + row) * CDIM + k0 + c16 * 8;
            *(float4*)(sAhi + dst) = *(const float4*)(Ahi + aoff);
            *(float4*)(sAlo + dst) = *(const float4*)(Alo + aoff);
            *(float4*)(sWhi + dst) = *(const float4*)(Whi + woff);
            *(float4*)(sWlo + dst) = *(const float4*)(Wlo + woff);
        }
        __syncthreads();

#pragma unroll
        for (int ks = 0; ks < 4; ++ks) {
            const uint32_t kb = ks * 32;      // 16 bf16 = 32 bytes per k-step
            uint32_t ah[2][4], al[2][4], bh[8][2], bl[8][2];
            ldmatrix_x4(ah[0], uAhi + kb);
            ldmatrix_x4(ah[1], uAhi + 16 * LDS * 2 + kb);
            ldmatrix_x4(al[0], uAlo + kb);
            ldmatrix_x4(al[1], uAlo + 16 * LDS * 2 + kb);
#pragma unroll
            for (int nj2 = 0; nj2 < 4; ++nj2) {
                uint32_t t[4];
                ldmatrix_x4(t, uWhi + nj2 * 16 * LDS * 2 + kb);
                bh[2 * nj2][0] = t[0]; bh[2 * nj2][1] = t[1];
                bh[2 * nj2 + 1][0] = t[2]; bh[2 * nj2 + 1][1] = t[3];
                ldmatrix_x4(t, uWlo + nj2 * 16 * LDS * 2 + kb);
                bl[2 * nj2][0] = t[0]; bl[2 * nj2][1] = t[1];
                bl[2 * nj2 + 1][0] = t[2]; bl[2 * nj2 + 1][1] = t[3];
            }
#pragma unroll
            for (int mi = 0; mi < 2; ++mi)
#pragma unroll
                for (int nj = 0; nj < 8; ++nj) {
                    mma16816(acc[mi][nj], ah[mi], bh[nj]);
                    mma16816(acc[mi][nj], ah[mi], bl[nj]);
                    mma16816(acc[mi][nj], al[mi], bh[nj]);
                }
        }
        __syncthreads();
    }

    // ---- epilogue: bias + store (float2, contiguous in both layouts) ----
    const int mrow0 = m0 + warp_m * 32 + (lane >> 2);
    const int ncol0 = n0 + warp_n * 64 + (lane & 3) * 2;
#pragma unroll
    for (int mi = 0; mi < 2; ++mi) {
#pragma unroll
        for (int nj = 0; nj < 8; ++nj) {
            int n = ncol0 + nj * 8;
            float b0 = bias[n], b1 = bias[n + 1];
#pragma unroll
            for (int half = 0; half < 2; ++half) {
                int m = mrow0 + mi * 16 + half * 8;
                float2 v;
                v.x = acc[mi][nj][half * 2 + 0] + b0;
                v.y = acc[mi][nj][half * 2 + 1] + b1;
                if (MODE == 0) {
                    *(float2*)&C[(size_t)m * CDIM + n] = v;
                } else {
                    int b = m >> 10, t = m & 1023;
                    int h = n >> 6,  d = n & 63;
                    *(float2*)&C[((((size_t)b * NHEADS + h) * TSEQ) + t) * HDIM + d] = v;
                }
            }
        }
    }
}

// ============================================================================
// Flash-style attention (unchanged). Q/K/V in [B,H,T,D] fp32.
// ============================================================================
__global__ void __launch_bounds__(128) attn_kernel(
    const float* __restrict__ Q,
    const float* __restrict__ K,
    const float* __restrict__ V,
    float* __restrict__ O)
{
    extern __shared__ float sh[];
    float* Ks = sh;                 // 64*64
    float* Vs = sh + 64 * 64;       // 64*64
    float* Ss = sh + 2 * 64 * 64;   // 128*65

    const int t   = threadIdx.x;
    const int bh  = blockIdx.y;
    const int row = blockIdx.x * 128 + t;
    const float scale = 0.125f;

    float q[64];
    const float* qptr = Q + ((size_t)bh * TSEQ + row) * HDIM;
#pragma unroll
    for (int d4 = 0; d4 < 16; d4++) {
        float4 v = *(const float4*)&qptr[d4 * 4];
        q[d4 * 4 + 0] = v.x * scale;
        q[d4 * 4 + 1] = v.y * scale;
        q[d4 * 4 + 2] = v.z * scale;
        q[d4 * 4 + 3] = v.w * scale;
    }

    float acc[64];
#pragma unroll
    for (int d = 0; d < 64; d++) acc[d] = 0.f;
    float mrow = -3.402823466e38f;
    float lsum = 0.f;

    const float* kbase = K + (size_t)bh * TSEQ * HDIM;
    const float* vbase = V + (size_t)bh * TSEQ * HDIM;

    for (int kt = 0; kt < TSEQ; kt += 64) {
        const float* ksrc = kbase + (size_t)kt * HDIM;
        const float* vsrc = vbase + (size_t)kt * HDIM;
#pragma unroll
        for (int it = 0; it < 8; it++) {
            int idx = (t + it * 128) * 4;
            *(float4*)&Ks[idx] = *(const float4*)&ksrc[idx];
            *(float4*)&Vs[idx] = *(const float4*)&vsrc[idx];
        }
        __syncthreads();

        float tm = -3.402823466e38f;
#pragma unroll 4
        for (int j = 0; j < 64; j++) {
            float s = 0.f;
#pragma unroll
            for (int d = 0; d < 64; d++) s += q[d] * Ks[j * 64 + d];
            Ss[t * 65 + j] = s;
            tm = fmaxf(tm, s);
        }

        float mn    = fmaxf(mrow, tm);
        float alpha = __expf(mrow - mn);
        mrow = mn;
        lsum *= alpha;
#pragma unroll
        for (int d = 0; d < 64; d++) acc[d] *= alpha;

#pragma unroll 2
        for (int j = 0; j < 64; j++) {
            float p = __expf(Ss[t * 65 + j] - mrow);
            lsum += p;
#pragma unroll
            for (int d = 0; d < 64; d++) acc[d] += p * Vs[j * 64 + d];
        }
        __syncthreads();
    }

    float inv = 1.f / lsum;
    int b = bh >> 4, h = bh & 15;
    float* optr = O + ((size_t)b * TSEQ + row) * CDIM + h * HDIM;
#pragma unroll
    for (int d4 = 0; d4 < 16; d4++) {
        float4 v;
        v.x = acc[d4 * 4 + 0] * inv;
        v.y = acc[d4 * 4 + 1] * inv;
        v.z = acc[d4 * 4 + 2] * inv;
        v.w = acc[d4 * 4 + 3] * inv;
        *(float4*)&optr[d4 * 4] = v;
    }
}

// ============================================================================
// kernel_launch
// ============================================================================
extern "C" void kernel_launch(void* const* d_in, const int* in_sizes, int n_in,
                              void* d_out, int out_size)
{
    const float* q  = (const float*)d_in[0];
    const float* k  = (const float*)d_in[1];
    const float* v  = (const float*)d_in[2];
    const float* Wq = (const float*)d_in[3];
    const float* bq = (const float*)d_in[4];
    const float* Wk = (const float*)d_in[5];
    const float* bk = (const float*)d_in[6];
    const float* Wv = (const float*)d_in[7];
    const float* bv = (const float*)d_in[8];
    const float* Wo = (const float*)d_in[9];
    const float* bo = (const float*)d_in[10];
    float* out = (float*)d_out;

    float *qp, *kp, *vp, *attn;
    __nv_bfloat16 *ahi, *alo, *whi, *wlo;
    cudaGetSymbolAddress((void**)&qp,   g_qp);
    cudaGetSymbolAddress((void**)&kp,   g_kp);
    cudaGetSymbolAddress((void**)&vp,   g_vp);
    cudaGetSymbolAddress((void**)&attn, g_attn);
    cudaGetSymbolAddress((void**)&ahi,  g_ahi);
    cudaGetSymbolAddress((void**)&alo,  g_alo);
    cudaGetSymbolAddress((void**)&whi,  g_whi);
    cudaGetSymbolAddress((void**)&wlo,  g_wlo);

    const int gemm_smem = 4 * 128 * LDS * (int)sizeof(__nv_bfloat16);  // 73728
    cudaFuncSetAttribute(gemm_mma_kernel<0>, cudaFuncAttributeMaxDynamicSharedMemorySize, gemm_smem);
    cudaFuncSetAttribute(gemm_mma_kernel<1>, cudaFuncAttributeMaxDynamicSharedMemorySize, gemm_smem);
    const int attn_smem = (64 * 64 * 2 + 128 * 65) * (int)sizeof(float);
    cudaFuncSetAttribute(attn_kernel, cudaFuncAttributeMaxDynamicSharedMemorySize, attn_smem);

    const int nA4 = M_ROWS * CDIM / 4;
    const int nW4 = CDIM * CDIM / 4;
    dim3 cgA((nA4 + 255) / 256), cgW((nW4 + 255) / 256), cblk(256);
    dim3 ggrid(CDIM / 128, M_ROWS / 128);  // (8, 32)

    // Q projection
    cvt_hilo_kernel<<<cgA, cblk>>>((const float4*)q,  (__nv_bfloat162*)ahi, (__nv_bfloat162*)alo, nA4);
    cvt_hilo_kernel<<<cgW, cblk>>>((const float4*)Wq, (__nv_bfloat162*)whi, (__nv_bfloat162*)wlo, nW4);
    gemm_mma_kernel<1><<<ggrid, 256, gemm_smem>>>(ahi, alo, whi, wlo, bq, qp);
    // K projection
    cvt_hilo_kernel<<<cgA, cblk>>>((const float4*)k,  (__nv_bfloat162*)ahi, (__nv_bfloat162*)alo, nA4);
    cvt_hilo_kernel<<<cgW, cblk>>>((const float4*)Wk, (__nv_bfloat162*)whi, (__nv_bfloat162*)wlo, nW4);
    gemm_mma_kernel<1><<<ggrid, 256, gemm_smem>>>(ahi, alo, whi, wlo, bk, kp);
    // V projection
    cvt_hilo_kernel<<<cgA, cblk>>>((const float4*)v,  (__nv_bfloat162*)ahi, (__nv_bfloat162*)alo, nA4);
    cvt_hilo_kernel<<<cgW, cblk>>>((const float4*)Wv, (__nv_bfloat162*)whi, (__nv_bfloat162*)wlo, nW4);
    gemm_mma_kernel<1><<<ggrid, 256, gemm_smem>>>(ahi, alo, whi, wlo, bv, vp);

    // attention
    dim3 agrid(TSEQ / 128, BATCH * NHEADS);
    attn_kernel<<<agrid, 128, attn_smem>>>(qp, kp, vp, attn);

    // output projection
    cvt_hilo_kernel<<<cgA, cblk>>>((const float4*)attn, (__nv_bfloat162*)ahi, (__nv_bfloat162*)alo, nA4);
    cvt_hilo_kernel<<<cgW, cblk>>>((const float4*)Wo,   (__nv_bfloat162*)whi, (__nv_bfloat162*)wlo, nW4);
    gemm_mma_kernel<0><<<ggrid, 256, gemm_smem>>>(ahi, alo, whi, wlo, bo, out);
}

// round 4
// speedup vs baseline: 2.7372x; 1.7600x over previous
#include <cuda_runtime.h>
#include <cuda_bf16.h>
#include <cstdint>

#define BATCH   4
#define TSEQ    1024
#define CDIM    1024
#define NHEADS  16
#define HDIM    64
#define M_ROWS  (BATCH * TSEQ)   // 4096
#define LDSA    72               // smem row stride in bf16 (64 data + 8 pad)

// ---------------- scratch (device globals; no allocations allowed) ----------
__device__ __nv_bfloat16 g_qhi[BATCH * NHEADS * TSEQ * HDIM];  // [B,H,T,D] (pre-scaled)
__device__ __nv_bfloat16 g_qlo[BATCH * NHEADS * TSEQ * HDIM];
__device__ __nv_bfloat16 g_khi[BATCH * NHEADS * TSEQ * HDIM];
__device__ __nv_bfloat16 g_klo[BATCH * NHEADS * TSEQ * HDIM];
__device__ __nv_bfloat16 g_vhi[BATCH * NHEADS * TSEQ * HDIM];
__device__ __nv_bfloat16 g_vlo[BATCH * NHEADS * TSEQ * HDIM];
__device__ float g_attn[M_ROWS * CDIM];                        // [B*T, C]
__device__ __nv_bfloat16 g_ahi[M_ROWS * CDIM];                 // GEMM A hi/lo
__device__ __nv_bfloat16 g_alo[M_ROWS * CDIM];
__device__ __nv_bfloat16 g_whi[CDIM * CDIM];                   // GEMM W hi/lo
__device__ __nv_bfloat16 g_wlo[CDIM * CDIM];

// ---------------- helpers ----------------------------------------------------
__device__ __forceinline__ uint32_t smem_u32(const void* p) {
    uint32_t a;
    asm("{ .reg .u64 t; cvta.to.shared.u64 t, %1; cvt.u32.u64 %0, t; }" : "=r"(a) : "l"(p));
    return a;
}
__device__ __forceinline__ void ldmatrix_x4(uint32_t* r, uint32_t addr) {
    asm volatile("ldmatrix.sync.aligned.m8n8.x4.shared.b16 {%0,%1,%2,%3}, [%4];"
        : "=r"(r[0]), "=r"(r[1]), "=r"(r[2]), "=r"(r[3]) : "r"(addr));
}
__device__ __forceinline__ void ldmatrix_x4_trans(uint32_t* r, uint32_t addr) {
    asm volatile("ldmatrix.sync.aligned.m8n8.x4.trans.shared.b16 {%0,%1,%2,%3}, [%4];"
        : "=r"(r[0]), "=r"(r[1]), "=r"(r[2]), "=r"(r[3]) : "r"(addr));
}
__device__ __forceinline__ void mma16816(float* d, const uint32_t* a, const uint32_t* b) {
    asm volatile("mma.sync.aligned.m16n8k16.row.col.f32.bf16.bf16.f32 "
        "{%0,%1,%2,%3}, {%4,%5,%6,%7}, {%8,%9}, {%0,%1,%2,%3};"
        : "+f"(d[0]), "+f"(d[1]), "+f"(d[2]), "+f"(d[3])
        : "r"(a[0]), "r"(a[1]), "r"(a[2]), "r"(a[3]), "r"(b[0]), "r"(b[1]));
}
// split (x,y) fp32 pair into packed bf16x2 hi and lo-residual
__device__ __forceinline__ void split2(float x, float y, uint32_t& hi, uint32_t& lo) {
    __nv_bfloat16 hx = __float2bfloat16(x), hy = __float2bfloat16(y);
    __nv_bfloat16 lx = __float2bfloat16(x - __bfloat162float(hx));
    __nv_bfloat16 ly = __float2bfloat16(y - __bfloat162float(hy));
    __nv_bfloat162 H; H.x = hx; H.y = hy;
    __nv_bfloat162 L; L.x = lx; L.y = ly;
    hi = *(uint32_t*)&H; lo = *(uint32_t*)&L;
}

// ============================================================================
// fp32 -> bf16 hi/lo split conversion (vectorized x4)
// ============================================================================
__global__ void __launch_bounds__(256) cvt_hilo_kernel(
    const float4* __restrict__ x,
    __nv_bfloat162* __restrict__ hi,
    __nv_bfloat162* __restrict__ lo,
    int n4)
{
    int i = blockIdx.x * blockDim.x + threadIdx.x;
    if (i >= n4) return;
    float4 v = x[i];
    uint32_t h0, l0, h1, l1;
    split2(v.x, v.y, h0, l0);
    split2(v.z, v.w, h1, l1);
    hi[2 * i] = *(__nv_bfloat162*)&h0; hi[2 * i + 1] = *(__nv_bfloat162*)&h1;
    lo[2 * i] = *(__nv_bfloat162*)&l0; lo[2 * i + 1] = *(__nv_bfloat162*)&l1;
}

// ============================================================================
// HMMA NT GEMM, hi/lo 3-pass:  C = A*W^T + bias
// MODE 0: fp32 row-major [M,N] -> Cf
// MODE 1: bf16 hi/lo head layout [B,H,T,D] -> Chi/Clo, value scaled by `scale`
// ============================================================================
template <int MODE>
__global__ void __launch_bounds__(256) gemm_mma_kernel(
    const __nv_bfloat16* __restrict__ Ahi, const __nv_bfloat16* __restrict__ Alo,
    const __nv_bfloat16* __restrict__ Whi, const __nv_bfloat16* __restrict__ Wlo,
    const float* __restrict__ bias,
    float* __restrict__ Cf,
    __nv_bfloat16* __restrict__ Chi, __nv_bfloat16* __restrict__ Clo,
    float scale)
{
    extern __shared__ __nv_bfloat16 sm[];
    __nv_bfloat16* sAhi = sm;
    __nv_bfloat16* sAlo = sm + 128 * LDSA;
    __nv_bfloat16* sWhi = sm + 2 * 128 * LDSA;
    __nv_bfloat16* sWlo = sm + 3 * 128 * LDSA;

    const int tid    = threadIdx.x;
    const int wid    = tid >> 5;
    const int lane   = tid & 31;
    const int warp_m = wid & 3;
    const int warp_n = wid >> 2;
    const int m0     = blockIdx.y * 128;
    const int n0     = blockIdx.x * 128;

    float acc[2][8][4];
#pragma unroll
    for (int i = 0; i < 2; i++)
#pragma unroll
        for (int j = 0; j < 8; j++)
#pragma unroll
            for (int r = 0; r < 4; r++) acc[i][j][r] = 0.f;

    const uint32_t aRowOff = (uint32_t)((warp_m * 32 + (lane & 15)) * LDSA * 2 + (lane >> 4) * 16);
    const uint32_t uAhi = smem_u32(sAhi) + aRowOff;
    const uint32_t uAlo = smem_u32(sAlo) + aRowOff;
    const uint32_t bRowOff = (uint32_t)((warp_n * 64 + (lane & 7) + ((lane >> 4) << 3)) * LDSA * 2
                                        + ((lane >> 3) & 1) * 16);
    const uint32_t uWhi = smem_u32(sWhi) + bRowOff;
    const uint32_t uWlo = smem_u32(sWlo) + bRowOff;

    for (int c = 0; c < 16; ++c) {
        const int k0 = c * 64;
#pragma unroll
        for (int rep = 0; rep < 4; ++rep) {
            int idx = tid + rep * 256;
            int row = idx >> 3;
            int c16 = idx & 7;
            int dst = row * LDSA + c16 * 8;
            size_t aoff = (size_t)(m0 + row) * CDIM + k0 + c16 * 8;
            size_t woff = (size_t)(n0 + row) * CDIM + k0 + c16 * 8;
            *(float4*)(sAhi + dst) = *(const float4*)(Ahi + aoff);
            *(float4*)(sAlo + dst) = *(const float4*)(Alo + aoff);
            *(float4*)(sWhi + dst) = *(const float4*)(Whi + woff);
            *(float4*)(sWlo + dst) = *(const float4*)(Wlo + woff);
        }
        __syncthreads();

#pragma unroll
        for (int ks = 0; ks < 4; ++ks) {
            const uint32_t kb = ks * 32;
            uint32_t ah[2][4], al[2][4], bh[8][2], bl[8][2];
            ldmatrix_x4(ah[0], uAhi + kb);
            ldmatrix_x4(ah[1], uAhi + 16 * LDSA * 2 + kb);
            ldmatrix_x4(al[0], uAlo + kb);
            ldmatrix_x4(al[1], uAlo + 16 * LDSA * 2 + kb);
#pragma unroll
            for (int nj2 = 0; nj2 < 4; ++nj2) {
                uint32_t t[4];
                ldmatrix_x4(t, uWhi + nj2 * 16 * LDSA * 2 + kb);
                bh[2 * nj2][0] = t[0]; bh[2 * nj2][1] = t[1];
                bh[2 * nj2 + 1][0] = t[2]; bh[2 * nj2 + 1][1] = t[3];
                ldmatrix_x4(t, uWlo + nj2 * 16 * LDSA * 2 + kb);
                bl[2 * nj2][0] = t[0]; bl[2 * nj2][1] = t[1];
                bl[2 * nj2 + 1][0] = t[2]; bl[2 * nj2 + 1][1] = t[3];
            }
#pragma unroll
            for (int mi = 0; mi < 2; ++mi)
#pragma unroll
                for (int nj = 0; nj < 8; ++nj) {
                    mma16816(acc[mi][nj], ah[mi], bh[nj]);
                    mma16816(acc[mi][nj], ah[mi], bl[nj]);
                    mma16816(acc[mi][nj], al[mi], bh[nj]);
                }
        }
        __syncthreads();
    }

    const int mrow0 = m0 + warp_m * 32 + (lane >> 2);
    const int ncol0 = n0 + warp_n * 64 + (lane & 3) * 2;
#pragma unroll
    for (int mi = 0; mi < 2; ++mi) {
#pragma unroll
        for (int nj = 0; nj < 8; ++nj) {
            int n = ncol0 + nj * 8;
            float b0 = bias[n], b1 = bias[n + 1];
#pragma unroll
            for (int half = 0; half < 2; ++half) {
                int m = mrow0 + mi * 16 + half * 8;
                float v0 = acc[mi][nj][half * 2 + 0] + b0;
                float v1 = acc[mi][nj][half * 2 + 1] + b1;
                if (MODE == 0) {
                    float2 v; v.x = v0; v.y = v1;
                    *(float2*)&Cf[(size_t)m * CDIM + n] = v;
                } else {
                    int b = m >> 10, t = m & 1023;
                    int h = n >> 6,  d = n & 63;
                    size_t o = ((((size_t)b * NHEADS + h) * TSEQ) + t) * HDIM + d;
                    uint32_t hi, lo;
                    split2(v0 * scale, v1 * scale, hi, lo);
                    *(uint32_t*)&Chi[o] = hi;
                    *(uint32_t*)&Clo[o] = lo;
                }
            }
        }
    }
}

// ============================================================================
// Flash attention on mma.sync (bf16 hi/lo, fp32 softmax).
// CTA: 128 q rows of one (b,h); 8 warps, each owns 16 q rows.
// KV tiles of 64. S = Qh*Kh + Ql*Kh + Qh*Kl ; PV = Ph*Vh + Pl*Vh + Ph*Vl.
// Output -> attn [B*T, C] fp32.
// ============================================================================
__global__ void __launch_bounds__(256) attn_mma_kernel(
    const __nv_bfloat16* __restrict__ Qh, const __nv_bfloat16* __restrict__ Ql,
    const __nv_bfloat16* __restrict__ Kh, const __nv_bfloat16* __restrict__ Kl,
    const __nv_bfloat16* __restrict__ Vh, const __nv_bfloat16* __restrict__ Vl,
    float* __restrict__ O)
{
    extern __shared__ __nv_bfloat16 sm[];
    __nv_bfloat16* sQh = sm;                       // 128*LDSA
    __nv_bfloat16* sQl = sm + 128 * LDSA;
    __nv_bfloat16* sKh = sm + 2 * 128 * LDSA;      // 64*LDSA each below
    __nv_bfloat16* sKl = sKh + 64 * LDSA;
    __nv_bfloat16* sVh = sKl + 64 * LDSA;
    __nv_bfloat16* sVl = sVh + 64 * LDSA;

    const int tid  = threadIdx.x;
    const int wid  = tid >> 5;
    const int lane = tid & 31;
    const int bh   = blockIdx.y;
    const int q0   = blockIdx.x * 128;
    const size_t bhBase = (size_t)bh * TSEQ * HDIM;

    // ---- load Q tile (128x64 hi/lo) ----
#pragma unroll
    for (int rep = 0; rep < 4; ++rep) {
        int idx = tid + rep * 256;            // 0..1023
        int row = idx >> 3;
        int c8  = idx & 7;
        size_t src = bhBase + (size_t)(q0 + row) * HDIM + c8 * 8;
        int dst = row * LDSA + c8 * 8;
        *(float4*)(sQh + dst) = *(const float4*)(Qh + src);
        *(float4*)(sQl + dst) = *(const float4*)(Ql + src);
    }
    __syncthreads();

    // ---- Q fragments (held in regs for whole kernel) ----
    uint32_t qh[4][4], ql[4][4];
    {
        uint32_t aOff = (uint32_t)((wid * 16 + (lane & 15)) * LDSA * 2 + (lane >> 4) * 16);
        uint32_t uQh = smem_u32(sQh) + aOff;
        uint32_t uQl = smem_u32(sQl) + aOff;
#pragma unroll
        for (int kt = 0; kt < 4; ++kt) {
            ldmatrix_x4(qh[kt], uQh + kt * 32);
            ldmatrix_x4(ql[kt], uQl + kt * 32);
        }
    }
    __syncthreads();   // Q fragments consumed; smem K/V region reused freely

    float o[8][4];
#pragma unroll
    for (int j = 0; j < 8; j++)
#pragma unroll
        for (int r = 0; r < 4; r++) o[j][r] = 0.f;
    float m0 = -3.402823466e38f, m1 = -3.402823466e38f;
    float l0 = 0.f, l1 = 0.f;

    // B-operand (K) address: non-trans ldmatrix on [n=kv][k=d] rows
    const uint32_t kOff = (uint32_t)(((lane & 7) + ((lane >> 4) << 3)) * LDSA * 2
                                     + ((lane >> 3) & 1) * 16);
    const uint32_t uKh = smem_u32(sKh) + kOff;
    const uint32_t uKl = smem_u32(sKl) + kOff;
    // B-operand (V) address: trans ldmatrix on [k=kv][n=d] rows
    const uint32_t vOff = (uint32_t)(((lane & 7) + ((lane >> 3) & 1) * 8) * LDSA * 2
                                     + ((lane >> 4) << 3) * 2);
    const uint32_t uVh = smem_u32(sVh) + vOff;
    const uint32_t uVl = smem_u32(sVl) + vOff;

    for (int it = 0; it < 16; ++it) {
        const int kv0 = it * 64;
        // ---- load K/V hi/lo tiles (64x64 each) ----
#pragma unroll
        for (int rep = 0; rep < 2; ++rep) {
            int idx = tid + rep * 256;        // 0..511
            int row = idx >> 3;
            int c8  = idx & 7;
            size_t src = bhBase + (size_t)(kv0 + row) * HDIM + c8 * 8;
            int dst = row * LDSA + c8 * 8;
            *(float4*)(sKh + dst) = *(const float4*)(Kh + src);
            *(float4*)(sKl + dst) = *(const float4*)(Kl + src);
            *(float4*)(sVh + dst) = *(const float4*)(Vh + src);
            *(float4*)(sVl + dst) = *(const float4*)(Vl + src);
        }
        __syncthreads();

        // ---- S = Q K^T (3 passes) ----
        float s[8][4];
#pragma unroll
        for (int j = 0; j < 8; j++)
#pragma unroll
            for (int r = 0; r < 4; r++) s[j][r] = 0.f;
#pragma unroll
        for (int kt = 0; kt < 4; ++kt) {
            const uint32_t kb = kt * 32;
            uint32_t bhf[8][2], blf[8][2];
#pragma unroll
            for (int nj2 = 0; nj2 < 4; ++nj2) {
                uint32_t t[4];
                ldmatrix_x4(t, uKh + nj2 * 16 * LDSA * 2 + kb);
                bhf[2 * nj2][0] = t[0]; bhf[2 * nj2][1] = t[1];
                bhf[2 * nj2 + 1][0] = t[2]; bhf[2 * nj2 + 1][1] = t[3];
                ldmatrix_x4(t, uKl + nj2 * 16 * LDSA * 2 + kb);
                blf[2 * nj2][0] = t[0]; blf[2 * nj2][1] = t[1];
                blf[2 * nj2 + 1][0] = t[2]; blf[2 * nj2 + 1][1] = t[3];
            }
#pragma unroll
            for (int nj = 0; nj < 8; ++nj) {
                mma16816(s[nj], qh[kt], bhf[nj]);
                mma16816(s[nj], ql[kt], bhf[nj]);
                mma16816(s[nj], qh[kt], blf[nj]);
            }
        }

        // ---- online softmax ----
        float tm0 = -3.402823466e38f, tm1 = -3.402823466e38f;
#pragma unroll
        for (int nj = 0; nj < 8; ++nj) {
            tm0 = fmaxf(tm0, fmaxf(s[nj][0], s[nj][1]));
            tm1 = fmaxf(tm1, fmaxf(s[nj][2], s[nj][3]));
        }
        tm0 = fmaxf(tm0, __shfl_xor_sync(0xffffffffu, tm0, 1));
        tm0 = fmaxf(tm0, __shfl_xor_sync(0xffffffffu, tm0, 2));
        tm1 = fmaxf(tm1, __shfl_xor_sync(0xffffffffu, tm1, 1));
        tm1 = fmaxf(tm1, __shfl_xor_sync(0xffffffffu, tm1, 2));
        float nm0 = fmaxf(m0, tm0), nm1 = fmaxf(m1, tm1);
        float a0 = __expf(m0 - nm0), a1 = __expf(m1 - nm1);
        m0 = nm0; m1 = nm1;
        l0 *= a0; l1 *= a1;
#pragma unroll
        for (int nj = 0; nj < 8; ++nj) {
            o[nj][0] *= a0; o[nj][1] *= a0;
            o[nj][2] *= a1; o[nj][3] *= a1;
        }

        // ---- P = exp(S - m), split hi/lo, repack as A fragments ----
        uint32_t ph[4][4], pl[4][4];
#pragma unroll
        for (int nj = 0; nj < 8; ++nj) {
            float p0 = __expf(s[nj][0] - m0);
            float p1 = __expf(s[nj][1] - m0);
            float p2 = __expf(s[nj][2] - m1);
            float p3 = __expf(s[nj][3] - m1);
            l0 += p0 + p1;
            l1 += p2 + p3;
            int kt = nj >> 1, hf = (nj & 1) * 2;
            split2(p0, p1, ph[kt][hf],     pl[kt][hf]);
            split2(p2, p3, ph[kt][hf + 1], pl[kt][hf + 1]);
        }

        // ---- O += P V (3 passes) ----
#pragma unroll
        for (int kt = 0; kt < 4; ++kt) {
            const uint32_t krow = kt * 16 * LDSA * 2;
#pragma unroll
            for (int ng = 0; ng < 4; ++ng) {
                uint32_t th[4], tl[4];
                ldmatrix_x4_trans(th, uVh + krow + ng * 32);
                ldmatrix_x4_trans(tl, uVl + krow + ng * 32);
                mma16816(o[2 * ng],     ph[kt], th);
                mma16816(o[2 * ng],     pl[kt], th);
                mma16816(o[2 * ng],     ph[kt], tl);
                mma16816(o[2 * ng + 1], ph[kt], th + 2);
                mma16816(o[2 * ng + 1], pl[kt], th + 2);
                mma16816(o[2 * ng + 1], ph[kt], tl + 2);
            }
        }
        __syncthreads();
    }

    // ---- finalize: normalize and write [B*T, C] ----
    l0 += __shfl_xor_sync(0xffffffffu, l0, 1);
    l0 += __shfl_xor_sync(0xffffffffu, l0, 2);
    l1 += __shfl_xor_sync(0xffffffffu, l1, 1);
    l1 += __shfl_xor_sync(0xffffffffu, l1, 2);
    float inv0 = 1.f / l0, inv1 = 1.f / l1;

    const int b = bh >> 4, h = bh & 15;
    const int r0 = q0 + wid * 16 + (lane >> 2);
    const int r1 = r0 + 8;
    const int c0 = h * HDIM + (lane & 3) * 2;
#pragma unroll
    for (int nj = 0; nj < 8; ++nj) {
        int c = c0 + nj * 8;
        float2 v0; v0.x = o[nj][0] * inv0; v0.y = o[nj][1] * inv0;
        float2 v1; v1.x = o[nj][2] * inv1; v1.y = o[nj][3] * inv1;
        *(float2*)&O[((size_t)b * TSEQ + r0) * CDIM + c] = v0;
        *(float2*)&O[((size_t)b * TSEQ + r1) * CDIM + c] = v1;
    }
}

// ============================================================================
// kernel_launch
// ============================================================================
extern "C" void kernel_launch(void* const* d_in, const int* in_sizes, int n_in,
                              void* d_out, int out_size)
{
    const float* q  = (const float*)d_in[0];
    const float* k  = (const float*)d_in[1];
    const float* v  = (const float*)d_in[2];
    const float* Wq = (const float*)d_in[3];
    const float* bq = (const float*)d_in[4];
    const float* Wk = (const float*)d_in[5];
    const float* bk = (const float*)d_in[6];
    const float* Wv = (const float*)d_in[7];
    const float* bv = (const float*)d_in[8];
    const float* Wo = (const float*)d_in[9];
    const float* bo = (const float*)d_in[10];
    float* out = (float*)d_out;

    float* attn;
    __nv_bfloat16 *qhi, *qlo, *khi, *klo, *vhi, *vlo, *ahi, *alo, *whi, *wlo;
    cudaGetSymbolAddress((void**)&attn, g_attn);
    cudaGetSymbolAddress((void**)&qhi,  g_qhi);
    cudaGetSymbolAddress((void**)&qlo,  g_qlo);
    cudaGetSymbolAddress((void**)&khi,  g_khi);
    cudaGetSymbolAddress((void**)&klo,  g_klo);
    cudaGetSymbolAddress((void**)&vhi,  g_vhi);
    cudaGetSymbolAddress((void**)&vlo,  g_vlo);
    cudaGetSymbolAddress((void**)&ahi,  g_ahi);
    cudaGetSymbolAddress((void**)&alo,  g_alo);
    cudaGetSymbolAddress((void**)&whi,  g_whi);
    cudaGetSymbolAddress((void**)&wlo,  g_wlo);

    const int gemm_smem = 4 * 128 * LDSA * (int)sizeof(__nv_bfloat16);          // 73728
    const int attn_smem = (2 * 128 + 4 * 64) * LDSA * (int)sizeof(__nv_bfloat16); // 73728
    cudaFuncSetAttribute(gemm_mma_kernel<0>, cudaFuncAttributeMaxDynamicSharedMemorySize, gemm_smem);
    cudaFuncSetAttribute(gemm_mma_kernel<1>, cudaFuncAttributeMaxDynamicSharedMemorySize, gemm_smem);
    cudaFuncSetAttribute(attn_mma_kernel, cudaFuncAttributeMaxDynamicSharedMemorySize, attn_smem);

    const int nA4 = M_ROWS * CDIM / 4;
    const int nW4 = CDIM * CDIM / 4;
    dim3 cgA((nA4 + 255) / 256), cgW((nW4 + 255) / 256), cblk(256);
    dim3 ggrid(CDIM / 128, M_ROWS / 128);  // (8, 32)

    // Q projection (scale 0.125 folded into hi/lo output)
    cvt_hilo_kernel<<<cgA, cblk>>>((const float4*)q,  (__nv_bfloat162*)ahi, (__nv_bfloat162*)alo, nA4);
    cvt_hilo_kernel<<<cgW, cblk>>>((const float4*)Wq, (__nv_bfloat162*)whi, (__nv_bfloat162*)wlo, nW4);
    gemm_mma_kernel<1><<<ggrid, 256, gemm_smem>>>(ahi, alo, whi, wlo, bq, nullptr, qhi, qlo, 0.125f);
    // K projection
    cvt_hilo_kernel<<<cgA, cblk>>>((const float4*)k,  (__nv_bfloat162*)ahi, (__nv_bfloat162*)alo, nA4);
    cvt_hilo_kernel<<<cgW, cblk>>>((const float4*)Wk, (__nv_bfloat162*)whi, (__nv_bfloat162*)wlo, nW4);
    gemm_mma_kernel<1><<<ggrid, 256, gemm_smem>>>(ahi, alo, whi, wlo, bk, nullptr, khi, klo, 1.0f);
    // V projection
    cvt_hilo_kernel<<<cgA, cblk>>>((const float4*)v,  (__nv_bfloat162*)ahi, (__nv_bfloat162*)alo, nA4);
    cvt_hilo_kernel<<<cgW, cblk>>>((const float4*)Wv, (__nv_bfloat162*)whi, (__nv_bfloat162*)wlo, nW4);
    gemm_mma_kernel<1><<<ggrid, 256, gemm_smem>>>(ahi, alo, whi, wlo, bv, nullptr, vhi, vlo, 1.0f);

    // attention
    dim3 agrid(TSEQ / 128, BATCH * NHEADS);  // (8, 64)
    attn_mma_kernel<<<agrid, 256, attn_smem>>>(qhi, qlo, khi, klo, vhi, vlo, attn);

    // output projection
    cvt_hilo_kernel<<<cgA, cblk>>>((const float4*)attn, (__nv_bfloat162*)ahi, (__nv_bfloat162*)alo, nA4);
    cvt_hilo_kernel<<<cgW, cblk>>>((const float4*)Wo,   (__nv_bfloat162*)whi, (__nv_bfloat162*)wlo, nW4);
    gemm_mma_kernel<0><<<ggrid, 256, gemm_smem>>>(ahi, alo, whi, wlo, bo, out, nullptr, nullptr, 1.0f);
}

// round 5
// speedup vs baseline: 2.9216x; 1.0674x over previous
#include <cuda_runtime.h>
#include <cuda_bf16.h>
#include <cstdint>

#define BATCH   4
#define TSEQ    1024
#define CDIM    1024
#define NHEADS  16
#define HDIM    64
#define M_ROWS  (BATCH * TSEQ)   // 4096
#define LDSA    72               // smem row stride in bf16 (64 data + 8 pad)

// ---------------- scratch (device globals; no allocations allowed) ----------
__device__ __nv_bfloat16 g_qhi[BATCH * NHEADS * TSEQ * HDIM];  // [B,H,T,D] (pre-scaled)
__device__ __nv_bfloat16 g_qlo[BATCH * NHEADS * TSEQ * HDIM];
__device__ __nv_bfloat16 g_khi[BATCH * NHEADS * TSEQ * HDIM];
__device__ __nv_bfloat16 g_klo[BATCH * NHEADS * TSEQ * HDIM];
__device__ __nv_bfloat16 g_vhi[BATCH * NHEADS * TSEQ * HDIM];
__device__ __nv_bfloat16 g_vlo[BATCH * NHEADS * TSEQ * HDIM];
__device__ __nv_bfloat16 g_ahi[3 * M_ROWS * CDIM];             // activations q,k,v (slot 0 reused for attn out)
__device__ __nv_bfloat16 g_alo[3 * M_ROWS * CDIM];
__device__ __nv_bfloat16 g_whi[4 * CDIM * CDIM];               // weights Wq,Wk,Wv,Wo
__device__ __nv_bfloat16 g_wlo[4 * CDIM * CDIM];

// ---------------- helpers ----------------------------------------------------
__device__ __forceinline__ uint32_t smem_u32(const void* p) {
    uint32_t a;
    asm("{ .reg .u64 t; cvta.to.shared.u64 t, %1; cvt.u32.u64 %0, t; }" : "=r"(a) : "l"(p));
    return a;
}
__device__ __forceinline__ void ldmatrix_x4(uint32_t* r, uint32_t addr) {
    asm volatile("ldmatrix.sync.aligned.m8n8.x4.shared.b16 {%0,%1,%2,%3}, [%4];"
        : "=r"(r[0]), "=r"(r[1]), "=r"(r[2]), "=r"(r[3]) : "r"(addr));
}
__device__ __forceinline__ void ldmatrix_x4_trans(uint32_t* r, uint32_t addr) {
    asm volatile("ldmatrix.sync.aligned.m8n8.x4.trans.shared.b16 {%0,%1,%2,%3}, [%4];"
        : "=r"(r[0]), "=r"(r[1]), "=r"(r[2]), "=r"(r[3]) : "r"(addr));
}
__device__ __forceinline__ void mma16816(float* d, const uint32_t* a, const uint32_t* b) {
    asm volatile("mma.sync.aligned.m16n8k16.row.col.f32.bf16.bf16.f32 "
        "{%0,%1,%2,%3}, {%4,%5,%6,%7}, {%8,%9}, {%0,%1,%2,%3};"
        : "+f"(d[0]), "+f"(d[1]), "+f"(d[2]), "+f"(d[3])
        : "r"(a[0]), "r"(a[1]), "r"(a[2]), "r"(a[3]), "r"(b[0]), "r"(b[1]));
}
__device__ __forceinline__ void cpa16(uint32_t dst, const void* src) {
    asm volatile("cp.async.cg.shared.global [%0], [%1], 16;" :: "r"(dst), "l"(src));
}
#define CP_COMMIT()  asm volatile("cp.async.commit_group;" ::: "memory")
#define CP_WAIT(n)   asm volatile("cp.async.wait_group %0;" :: "n"(n) : "memory")

// split (x,y) fp32 pair into packed bf16x2 hi and lo-residual
__device__ __forceinline__ void split2(float x, float y, uint32_t& hi, uint32_t& lo) {
    __nv_bfloat16 hx = __float2bfloat16(x), hy = __float2bfloat16(y);
    __nv_bfloat16 lx = __float2bfloat16(x - __bfloat162float(hx));
    __nv_bfloat16 ly = __float2bfloat16(y - __bfloat162float(hy));
    __nv_bfloat162 H; H.x = hx; H.y = hy;
    __nv_bfloat162 L; L.x = lx; L.y = ly;
    hi = *(uint32_t*)&H; lo = *(uint32_t*)&L;
}

// ============================================================================
// Batched fp32 -> bf16 hi/lo split (up to 4 tensors per launch; blockIdx.y picks)
// ============================================================================
struct CvtBatch {
    const float4*    src[4];
    __nv_bfloat162*  hi[4];
    __nv_bfloat162*  lo[4];
};
__global__ void __launch_bounds__(256) cvt_batch_kernel(CvtBatch p, int n4)
{
    int w = blockIdx.y;
    int i = blockIdx.x * blockDim.x + threadIdx.x;
    if (i >= n4) return;
    float4 v = p.src[w][i];
    uint32_t h0, l0, h1, l1;
    split2(v.x, v.y, h0, l0);
    split2(v.z, v.w, h1, l1);
    p.hi[w][2 * i] = *(__nv_bfloat162*)&h0; p.hi[w][2 * i + 1] = *(__nv_bfloat162*)&h1;
    p.lo[w][2 * i] = *(__nv_bfloat162*)&l0; p.lo[w][2 * i + 1] = *(__nv_bfloat162*)&l1;
}

// ============================================================================
// HMMA NT GEMM, hi/lo 3-pass, 2-stage cp.async pipeline:
//   C = A*W^T + bias
// MODE 0: fp32 row-major [M,N] -> Cf
// MODE 1: bf16 hi/lo head layout [B,H,T,D] -> Chi/Clo, scaled by `scale`
// ============================================================================
#define G_STAGE_ELEMS (4 * 128 * LDSA)          // bf16 units per stage
#define G_STAGE_BYTES (G_STAGE_ELEMS * 2)       // 73728
#define OFF_AHI 0
#define OFF_ALO (128 * LDSA * 2)
#define OFF_WHI (2 * 128 * LDSA * 2)
#define OFF_WLO (3 * 128 * LDSA * 2)

template <int MODE>
__global__ void __launch_bounds__(256) gemm_mma_kernel(
    const __nv_bfloat16* __restrict__ Ahi, const __nv_bfloat16* __restrict__ Alo,
    const __nv_bfloat16* __restrict__ Whi, const __nv_bfloat16* __restrict__ Wlo,
    const float* __restrict__ bias,
    float* __restrict__ Cf,
    __nv_bfloat16* __restrict__ Chi, __nv_bfloat16* __restrict__ Clo,
    float scale)
{
    extern __shared__ __nv_bfloat16 sm[];
    const uint32_t sbase = smem_u32(sm);

    const int tid    = threadIdx.x;
    const int wid    = tid >> 5;
    const int lane   = tid & 31;
    const int warp_m = wid & 3;
    const int warp_n = wid >> 2;
    const int m0     = blockIdx.y * 128;
    const int n0     = blockIdx.x * 128;

    float acc[2][8][4];
#pragma unroll
    for (int i = 0; i < 2; i++)
#pragma unroll
        for (int j = 0; j < 8; j++)
#pragma unroll
            for (int r = 0; r < 4; r++) acc[i][j][r] = 0.f;

    // loader lane geometry (per stage): 4 reps x 4 arrays, 16B each
    const int lrow = 0;  // computed per rep
    // ldmatrix lane offsets (within a stage)
    const uint32_t aRowOff = (uint32_t)((warp_m * 32 + (lane & 15)) * LDSA * 2 + (lane >> 4) * 16);
    const uint32_t bRowOff = (uint32_t)((warp_n * 64 + (lane & 7) + ((lane >> 4) << 3)) * LDSA * 2
                                        + ((lane >> 3) & 1) * 16);
    (void)lrow;

    auto load_stage = [&](int stage, int k0) {
        const uint32_t sb = sbase + stage * G_STAGE_BYTES;
#pragma unroll
        for (int rep = 0; rep < 4; ++rep) {
            int idx = tid + rep * 256;
            int row = idx >> 3;
            int c16 = idx & 7;
            uint32_t dst = (uint32_t)((row * LDSA + c16 * 8) * 2);
            size_t aoff = (size_t)(m0 + row) * CDIM + k0 + c16 * 8;
            size_t woff = (size_t)(n0 + row) * CDIM + k0 + c16 * 8;
            cpa16(sb + OFF_AHI + dst, Ahi + aoff);
            cpa16(sb + OFF_ALO + dst, Alo + aoff);
            cpa16(sb + OFF_WHI + dst, Whi + woff);
            cpa16(sb + OFF_WLO + dst, Wlo + woff);
        }
    };

    load_stage(0, 0);
    CP_COMMIT();

    for (int c = 0; c < 16; ++c) {
        if (c < 15) {
            load_stage((c + 1) & 1, (c + 1) * 64);
            CP_COMMIT();
            CP_WAIT(1);
        } else {
            CP_WAIT(0);
        }
        __syncthreads();

        const uint32_t sb  = sbase + (c & 1) * G_STAGE_BYTES;
        const uint32_t uAh = sb + OFF_AHI + aRowOff;
        const uint32_t uAl = sb + OFF_ALO + aRowOff;
        const uint32_t uWh = sb + OFF_WHI + bRowOff;
        const uint32_t uWl = sb + OFF_WLO + bRowOff;

#pragma unroll
        for (int ks = 0; ks < 4; ++ks) {
            const uint32_t kb = ks * 32;
            uint32_t ah[2][4], al[2][4], bh[8][2], bl[8][2];
            ldmatrix_x4(ah[0], uAh + kb);
            ldmatrix_x4(ah[1], uAh + 16 * LDSA * 2 + kb);
            ldmatrix_x4(al[0], uAl + kb);
            ldmatrix_x4(al[1], uAl + 16 * LDSA * 2 + kb);
#pragma unroll
            for (int nj2 = 0; nj2 < 4; ++nj2) {
                uint32_t t[4];
                ldmatrix_x4(t, uWh + nj2 * 16 * LDSA * 2 + kb);
                bh[2 * nj2][0] = t[0]; bh[2 * nj2][1] = t[1];
                bh[2 * nj2 + 1][0] = t[2]; bh[2 * nj2 + 1][1] = t[3];
                ldmatrix_x4(t, uWl + nj2 * 16 * LDSA * 2 + kb);
                bl[2 * nj2][0] = t[0]; bl[2 * nj2][1] = t[1];
                bl[2 * nj2 + 1][0] = t[2]; bl[2 * nj2 + 1][1] = t[3];
            }
#pragma unroll
            for (int mi = 0; mi < 2; ++mi)
#pragma unroll
                for (int nj = 0; nj < 8; ++nj) {
                    mma16816(acc[mi][nj], ah[mi], bh[nj]);
                    mma16816(acc[mi][nj], ah[mi], bl[nj]);
                    mma16816(acc[mi][nj], al[mi], bh[nj]);
                }
        }
        __syncthreads();
    }

    const int mrow0 = m0 + warp_m * 32 + (lane >> 2);
    const int ncol0 = n0 + warp_n * 64 + (lane & 3) * 2;
#pragma unroll
    for (int mi = 0; mi < 2; ++mi) {
#pragma unroll
        for (int nj = 0; nj < 8; ++nj) {
            int n = ncol0 + nj * 8;
            float b0 = bias[n], b1 = bias[n + 1];
#pragma unroll
            for (int half = 0; half < 2; ++half) {
                int m = mrow0 + mi * 16 + half * 8;
                float v0 = acc[mi][nj][half * 2 + 0] + b0;
                float v1 = acc[mi][nj][half * 2 + 1] + b1;
                if (MODE == 0) {
                    float2 v; v.x = v0; v.y = v1;
                    *(float2*)&Cf[(size_t)m * CDIM + n] = v;
                } else {
                    int b = m >> 10, t = m & 1023;
                    int h = n >> 6,  d = n & 63;
                    size_t o = ((((size_t)b * NHEADS + h) * TSEQ) + t) * HDIM + d;
                    uint32_t hi, lo;
                    split2(v0 * scale, v1 * scale, hi, lo);
                    *(uint32_t*)&Chi[o] = hi;
                    *(uint32_t*)&Clo[o] = lo;
                }
            }
        }
    }
}

// ============================================================================
// Flash attention on mma.sync, 2-stage cp.async K/V pipeline.
// CTA: 128 q rows of one (b,h); 8 warps x 16 rows. KV tiles of 64.
// Output: bf16 hi/lo [B*T, C] (feeds output projection directly).
// ============================================================================
#define KV_STAGE_BYTES (4 * 64 * LDSA * 2)   // 36864
#define OFF_KH 0
#define OFF_KL (64 * LDSA * 2)
#define OFF_VH (2 * 64 * LDSA * 2)
#define OFF_VL (3 * 64 * LDSA * 2)

__global__ void __launch_bounds__(256) attn_mma_kernel(
    const __nv_bfloat16* __restrict__ Qh, const __nv_bfloat16* __restrict__ Ql,
    const __nv_bfloat16* __restrict__ Kh, const __nv_bfloat16* __restrict__ Kl,
    const __nv_bfloat16* __restrict__ Vh, const __nv_bfloat16* __restrict__ Vl,
    __nv_bfloat16* __restrict__ Ohi, __nv_bfloat16* __restrict__ Olo)
{
    extern __shared__ __nv_bfloat16 sm[];
    __nv_bfloat16* sQh = sm;                       // 128*LDSA
    __nv_bfloat16* sQl = sm + 128 * LDSA;
    const uint32_t kvbase = smem_u32(sm + 2 * 128 * LDSA);

    const int tid  = threadIdx.x;
    const int wid  = tid >> 5;
    const int lane = tid & 31;
    const int bh   = blockIdx.y;
    const int q0   = blockIdx.x * 128;
    const size_t bhBase = (size_t)bh * TSEQ * HDIM;

    auto load_kv = [&](int stage, int kv0) {
        const uint32_t sb = kvbase + stage * KV_STAGE_BYTES;
#pragma unroll
        for (int rep = 0; rep < 2; ++rep) {
            int idx = tid + rep * 256;
            int row = idx >> 3;
            int c8  = idx & 7;
            uint32_t dst = (uint32_t)((row * LDSA + c8 * 8) * 2);
            size_t src = bhBase + (size_t)(kv0 + row) * HDIM + c8 * 8;
            cpa16(sb + OFF_KH + dst, Kh + src);
            cpa16(sb + OFF_KL + dst, Kl + src);
            cpa16(sb + OFF_VH + dst, Vh + src);
            cpa16(sb + OFF_VL + dst, Vl + src);
        }
    };

    // kick off KV stage 0 before touching Q
    load_kv(0, 0);
    CP_COMMIT();

    // ---- load Q tile (128x64 hi/lo) ----
#pragma unroll
    for (int rep = 0; rep < 4; ++rep) {
        int idx = tid + rep * 256;
        int row = idx >> 3;
        int c8  = idx & 7;
        size_t src = bhBase + (size_t)(q0 + row) * HDIM + c8 * 8;
        int dst = row * LDSA + c8 * 8;
        *(float4*)(sQh + dst) = *(const float4*)(Qh + src);
        *(float4*)(sQl + dst) = *(const float4*)(Ql + src);
    }
    __syncthreads();

    // ---- Q fragments (held in regs) ----
    uint32_t qh[4][4], ql[4][4];
    {
        uint32_t aOff = (uint32_t)((wid * 16 + (lane & 15)) * LDSA * 2 + (lane >> 4) * 16);
        uint32_t uQh = smem_u32(sQh) + aOff;
        uint32_t uQl = smem_u32(sQl) + aOff;
#pragma unroll
        for (int kt = 0; kt < 4; ++kt) {
            ldmatrix_x4(qh[kt], uQh + kt * 32);
            ldmatrix_x4(ql[kt], uQl + kt * 32);
        }
    }

    float o[8][4];
#pragma unroll
    for (int j = 0; j < 8; j++)
#pragma unroll
        for (int r = 0; r < 4; r++) o[j][r] = 0.f;
    float m0 = -3.402823466e38f, m1 = -3.402823466e38f;
    float l0 = 0.f, l1 = 0.f;

    const uint32_t kOff = (uint32_t)(((lane & 7) + ((lane >> 4) << 3)) * LDSA * 2
                                     + ((lane >> 3) & 1) * 16);
    const uint32_t vOff = (uint32_t)(((lane & 7) + ((lane >> 3) & 1) * 8) * LDSA * 2
                                     + ((lane >> 4) << 3) * 2);

    for (int it = 0; it < 16; ++it) {
        if (it < 15) {
            load_kv((it + 1) & 1, (it + 1) * 64);
            CP_COMMIT();
            CP_WAIT(1);
        } else {
            CP_WAIT(0);
        }
        __syncthreads();

        const uint32_t sb  = kvbase + (it & 1) * KV_STAGE_BYTES;
        const uint32_t uKh = sb + OFF_KH + kOff;
        const uint32_t uKl = sb + OFF_KL + kOff;
        const uint32_t uVh = sb + OFF_VH + vOff;
        const uint32_t uVl = sb + OFF_VL + vOff;

        // ---- S = Q K^T (3 passes) ----
        float s[8][4];
#pragma unroll
        for (int j = 0; j < 8; j++)
#pragma unroll
            for (int r = 0; r < 4; r++) s[j][r] = 0.f;
#pragma unroll
        for (int kt = 0; kt < 4; ++kt) {
            const uint32_t kb = kt * 32;
            uint32_t bhf[8][2], blf[8][2];
#pragma unroll
            for (int nj2 = 0; nj2 < 4; ++nj2) {
                uint32_t t[4];
                ldmatrix_x4(t, uKh + nj2 * 16 * LDSA * 2 + kb);
                bhf[2 * nj2][0] = t[0]; bhf[2 * nj2][1] = t[1];
                bhf[2 * nj2 + 1][0] = t[2]; bhf[2 * nj2 + 1][1] = t[3];
                ldmatrix_x4(t, uKl + nj2 * 16 * LDSA * 2 + kb);
                blf[2 * nj2][0] = t[0]; blf[2 * nj2][1] = t[1];
                blf[2 * nj2 + 1][0] = t[2]; blf[2 * nj2 + 1][1] = t[3];
            }
#pragma unroll
            for (int nj = 0; nj < 8; ++nj) {
                mma16816(s[nj], qh[kt], bhf[nj]);
                mma16816(s[nj], ql[kt], bhf[nj]);
                mma16816(s[nj], qh[kt], blf[nj]);
            }
        }

        // ---- online softmax ----
        float tm0 = -3.402823466e38f, tm1 = -3.402823466e38f;
#pragma unroll
        for (int nj = 0; nj < 8; ++nj) {
            tm0 = fmaxf(tm0, fmaxf(s[nj][0], s[nj][1]));
            tm1 = fmaxf(tm1, fmaxf(s[nj][2], s[nj][3]));
        }
        tm0 = fmaxf(tm0, __shfl_xor_sync(0xffffffffu, tm0, 1));
        tm0 = fmaxf(tm0, __shfl_xor_sync(0xffffffffu, tm0, 2));
        tm1 = fmaxf(tm1, __shfl_xor_sync(0xffffffffu, tm1, 1));
        tm1 = fmaxf(tm1, __shfl_xor_sync(0xffffffffu, tm1, 2));
        float nm0 = fmaxf(m0, tm0), nm1 = fmaxf(m1, tm1);
        float a0 = __expf(m0 - nm0), a1 = __expf(m1 - nm1);
        m0 = nm0; m1 = nm1;
        l0 *= a0; l1 *= a1;
#pragma unroll
        for (int nj = 0; nj < 8; ++nj) {
            o[nj][0] *= a0; o[nj][1] *= a0;
            o[nj][2] *= a1; o[nj][3] *= a1;
        }

        // ---- P = exp(S - m), split hi/lo into A fragments ----
        uint32_t ph[4][4], pl[4][4];
#pragma unroll
        for (int nj = 0; nj < 8; ++nj) {
            float p0 = __expf(s[nj][0] - m0);
            float p1 = __expf(s[nj][1] - m0);
            float p2 = __expf(s[nj][2] - m1);
            float p3 = __expf(s[nj][3] - m1);
            l0 += p0 + p1;
            l1 += p2 + p3;
            int kt = nj >> 1, hf = (nj & 1) * 2;
            split2(p0, p1, ph[kt][hf],     pl[kt][hf]);
            split2(p2, p3, ph[kt][hf + 1], pl[kt][hf + 1]);
        }

        // ---- O += P V (3 passes) ----
#pragma unroll
        for (int kt = 0; kt < 4; ++kt) {
            const uint32_t krow = kt * 16 * LDSA * 2;
#pragma unroll
            for (int ng = 0; ng < 4; ++ng) {
                uint32_t th[4], tl[4];
                ldmatrix_x4_trans(th, uVh + krow + ng * 32);
                ldmatrix_x4_trans(tl, uVl + krow + ng * 32);
                mma16816(o[2 * ng],     ph[kt], th);
                mma16816(o[2 * ng],     pl[kt], th);
                mma16816(o[2 * ng],     ph[kt], tl);
                mma16816(o[2 * ng + 1], ph[kt], th + 2);
                mma16816(o[2 * ng + 1], pl[kt], th + 2);
                mma16816(o[2 * ng + 1], ph[kt], tl + 2);
            }
        }
        __syncthreads();
    }

    // ---- finalize: normalize, split hi/lo, write [B*T, C] ----
    l0 += __shfl_xor_sync(0xffffffffu, l0, 1);
    l0 += __shfl_xor_sync(0xffffffffu, l0, 2);
    l1 += __shfl_xor_sync(0xffffffffu, l1, 1);
    l1 += __shfl_xor_sync(0xffffffffu, l1, 2);
    float inv0 = 1.f / l0, inv1 = 1.f / l1;

    const int b = bh >> 4, h = bh & 15;
    const int r0 = q0 + wid * 16 + (lane >> 2);
    const int r1 = r0 + 8;
    const int c0 = h * HDIM + (lane & 3) * 2;
#pragma unroll
    for (int nj = 0; nj < 8; ++nj) {
        int c = c0 + nj * 8;
        size_t i0 = ((size_t)b * TSEQ + r0) * CDIM + c;
        size_t i1 = ((size_t)b * TSEQ + r1) * CDIM + c;
        uint32_t hi, lo;
        split2(o[nj][0] * inv0, o[nj][1] * inv0, hi, lo);
        *(uint32_t*)&Ohi[i0] = hi; *(uint32_t*)&Olo[i0] = lo;
        split2(o[nj][2] * inv1, o[nj][3] * inv1, hi, lo);
        *(uint32_t*)&Ohi[i1] = hi; *(uint32_t*)&Olo[i1] = lo;
    }
}

// ============================================================================
// kernel_launch
// ============================================================================
extern "C" void kernel_launch(void* const* d_in, const int* in_sizes, int n_in,
                              void* d_out, int out_size)
{
    const float* q  = (const float*)d_in[0];
    const float* k  = (const float*)d_in[1];
    const float* v  = (const float*)d_in[2];
    const float* Wq = (const float*)d_in[3];
    const float* bq = (const float*)d_in[4];
    const float* Wk = (const float*)d_in[5];
    const float* bk = (const float*)d_in[6];
    const float* Wv = (const float*)d_in[7];
    const float* bv = (const float*)d_in[8];
    const float* Wo = (const float*)d_in[9];
    const float* bo = (const float*)d_in[10];
    float* out = (float*)d_out;

    __nv_bfloat16 *qhi, *qlo, *khi, *klo, *vhi, *vlo, *ahi, *alo, *whi, *wlo;
    cudaGetSymbolAddress((void**)&qhi, g_qhi);
    cudaGetSymbolAddress((void**)&qlo, g_qlo);
    cudaGetSymbolAddress((void**)&khi, g_khi);
    cudaGetSymbolAddress((void**)&klo, g_klo);
    cudaGetSymbolAddress((void**)&vhi, g_vhi);
    cudaGetSymbolAddress((void**)&vlo, g_vlo);
    cudaGetSymbolAddress((void**)&ahi, g_ahi);
    cudaGetSymbolAddress((void**)&alo, g_alo);
    cudaGetSymbolAddress((void**)&whi, g_whi);
    cudaGetSymbolAddress((void**)&wlo, g_wlo);

    const size_t ASZ = (size_t)M_ROWS * CDIM;   // activation elements
    const size_t WSZ = (size_t)CDIM * CDIM;     // weight elements

    const int gemm_smem = 2 * G_STAGE_BYTES;                               // 147456
    const int attn_smem = 2 * 128 * LDSA * 2 + 2 * KV_STAGE_BYTES;         // 110592
    cudaFuncSetAttribute(gemm_mma_kernel<0>, cudaFuncAttributeMaxDynamicSharedMemorySize, gemm_smem);
    cudaFuncSetAttribute(gemm_mma_kernel<1>, cudaFuncAttributeMaxDynamicSharedMemorySize, gemm_smem);
    cudaFuncSetAttribute(attn_mma_kernel, cudaFuncAttributeMaxDynamicSharedMemorySize, attn_smem);

    // ---- batched conversions ----
    CvtBatch wb;
    wb.src[0] = (const float4*)Wq; wb.src[1] = (const float4*)Wk;
    wb.src[2] = (const float4*)Wv; wb.src[3] = (const float4*)Wo;
    for (int i = 0; i < 4; i++) {
        wb.hi[i] = (__nv_bfloat162*)(whi + i * WSZ);
        wb.lo[i] = (__nv_bfloat162*)(wlo + i * WSZ);
    }
    int nW4 = (int)(WSZ / 4);
    cvt_batch_kernel<<<dim3((nW4 + 255) / 256, 4), 256>>>(wb, nW4);

    CvtBatch ab;
    ab.src[0] = (const float4*)q; ab.src[1] = (const float4*)k;
    ab.src[2] = (const float4*)v; ab.src[3] = (const float4*)q;  // unused slot
    for (int i = 0; i < 4; i++) {
        int j = i < 3 ? i : 0;
        ab.hi[i] = (__nv_bfloat162*)(ahi + j * ASZ);
        ab.lo[i] = (__nv_bfloat162*)(alo + j * ASZ);
    }
    int nA4 = (int)(ASZ / 4);
    cvt_batch_kernel<<<dim3((nA4 + 255) / 256, 3), 256>>>(ab, nA4);

    dim3 ggrid(CDIM / 128, M_ROWS / 128);  // (8, 32)

    // projections (Q scale 0.125 folded into hi/lo output)
    gemm_mma_kernel<1><<<ggrid, 256, gemm_smem>>>(ahi + 0 * ASZ, alo + 0 * ASZ,
        whi + 0 * WSZ, wlo + 0 * WSZ, bq, nullptr, qhi, qlo, 0.125f);
    gemm_mma_kernel<1><<<ggrid, 256, gemm_smem>>>(ahi + 1 * ASZ, alo + 1 * ASZ,
        whi + 1 * WSZ, wlo + 1 * WSZ, bk, nullptr, khi, klo, 1.0f);
    gemm_mma_kernel<1><<<ggrid, 256, gemm_smem>>>(ahi + 2 * ASZ, alo + 2 * ASZ,
        whi + 2 * WSZ, wlo + 2 * WSZ, bv, nullptr, vhi, vlo, 1.0f);

    // attention -> hi/lo activations (reuse slot 0)
    dim3 agrid(TSEQ / 128, BATCH * NHEADS);  // (8, 64)
    attn_mma_kernel<<<agrid, 256, attn_smem>>>(qhi, qlo, khi, klo, vhi, vlo,
                                               ahi + 0 * ASZ, alo + 0 * ASZ);

    // output projection
    gemm_mma_kernel<0><<<ggrid, 256, gemm_smem>>>(ahi + 0 * ASZ, alo + 0 * ASZ,
        whi + 3 * WSZ, wlo + 3 * WSZ, bo, out, nullptr, nullptr, 1.0f);
}